// round 5
// baseline (speedup 1.0000x reference)
#include <cuda_runtime.h>
#include <math.h>
#include <float.h>

#define NN 100000
#define BB 64
#define EE 1600000
#define DH 128
#define NCLS 3
#define TOLV 1e-7f
#define BN_EPSV 1e-5f
#define MIN_SCORE 0.1f
#define KBWORDS ((NN + 31) / 32)

#define GRID 148
#define NT 1024
#define TOT (GRID * NT)
#define SUB (NT / DH)            // 8 nodes per block in fused MLP
#define E4TOT (EE / 4)           // 400000 int4 chunks of src array
#define EPB ((E4TOT + GRID - 1) / GRID)   // 2704 int4 per block (43.3 KB smem)

// ---------------- persistent device scratch ----------------
// g_kbits / g_nk / g_nce rely on zero-init for the first run and are
// restored to zero at the END of every run (deterministic per-call state).
__device__ unsigned g_bar_count = 0;
__device__ unsigned g_bar_gen = 0;

__device__ int   g_nk;
__device__ int   g_nce;
__device__ float g_logit[NN];
__device__ int   g_kidx[NN];          // compact pos -> node id (for cleanup)
__device__ int   g_kgraph[NN];        // compact pos -> graph id
__device__ int   g_cidx[NN];
__device__ unsigned g_kbits[KBWORDS];
__device__ float g_h0[NN * 2];
__device__ int   g_esrc[EE];
__device__ int   g_edst[EE];
__device__ float g_degc[NN];
__device__ float g_agg[NN * DH];
__device__ float g_hA[NN * DH];
__device__ float g_hB[NN * DH];
__device__ float g_pool[BB * DH];
__device__ float g_sink;              // dead-store target for L2-warm loads

__device__ __forceinline__ void atomicMaxF(float* addr, float v) {
    if (v >= 0.0f) atomicMax((int*)addr, __float_as_int(v));
    else           atomicMin((unsigned int*)addr, __float_as_uint(v));
}

// Software grid barrier; all GRID blocks co-resident (1 block/SM).
__device__ __forceinline__ void grid_barrier() {
    __syncthreads();
    if (threadIdx.x == 0) {
        unsigned gen = *(volatile unsigned*)&g_bar_gen;   // read BEFORE arriving
        __threadfence();                                  // release prior writes
        unsigned ticket = atomicAdd(&g_bar_count, 1u);
        if (ticket == GRID - 1) {
            g_bar_count = 0;
            __threadfence();
            atomicAdd(&g_bar_gen, 1u);                    // release
        } else {
            unsigned g;
            for (;;) {
                asm volatile("ld.acquire.gpu.u32 %0, [%1];"
                             : "=r"(g) : "l"(&g_bar_gen) : "memory");
                if (g != gen) break;
                __nanosleep(32);
            }
        }
    }
    __syncthreads();
}

__device__ __forceinline__ void cp_async16(void* smem_dst, const void* gmem_src) {
    unsigned s;
    asm("{ .reg .u64 t; cvta.to.shared.u64 t, %1; cvt.u32.u64 %0, t; }"
        : "=r"(s) : "l"(smem_dst));
    asm volatile("cp.async.cg.shared.global [%0], [%1], 16;"
                 :: "r"(s), "l"(gmem_src) : "memory");
}

// ---------------- block reductions (shared red[32]) ----------------
__device__ __forceinline__ float blk_max(float v, float* red) {
    for (int o = 16; o > 0; o >>= 1) v = fmaxf(v, __shfl_xor_sync(~0u, v, o));
    if ((threadIdx.x & 31) == 0) red[threadIdx.x >> 5] = v;
    __syncthreads();
    if (threadIdx.x < 32) {
        float w = (threadIdx.x < NT / 32) ? red[threadIdx.x] : -FLT_MAX;
        for (int o = 16; o > 0; o >>= 1) w = fmaxf(w, __shfl_xor_sync(~0u, w, o));
        if (threadIdx.x == 0) red[0] = w;
    }
    __syncthreads();
    float r = red[0];
    __syncthreads();
    return r;
}
__device__ __forceinline__ float blk_sum(float v, float* red) {
    for (int o = 16; o > 0; o >>= 1) v += __shfl_xor_sync(~0u, v, o);
    if ((threadIdx.x & 31) == 0) red[threadIdx.x >> 5] = v;
    __syncthreads();
    if (threadIdx.x < 32) {
        float w = (threadIdx.x < NT / 32) ? red[threadIdx.x] : 0.0f;
        for (int o = 16; o > 0; o >>= 1) w += __shfl_xor_sync(~0u, w, o);
        if (threadIdx.x == 0) red[0] = w;
    }
    __syncthreads();
    float r = red[0];
    __syncthreads();
    return r;
}

__device__ __forceinline__ int lbound(const int* __restrict__ a, int val) {
    int lo = 0, hi = NN;
    while (lo < hi) {
        int m = (lo + hi) >> 1;
        if (__ldg(&a[m]) < val) lo = m + 1; else hi = m;
    }
    return lo;
}

// General-path GCN layer (128->128) + bias/relu/bn (used only when nce > 0).
__device__ void gcn_layer128(int tid, int nk, int nce,
                             const float* __restrict__ hin, float* __restrict__ hout,
                             const float* __restrict__ W, const float* __restrict__ b,
                             const float* __restrict__ g, const float* __restrict__ be,
                             const float* __restrict__ rm, const float* __restrict__ rv,
                             bool do_pool) {
    for (int t = tid; t < nk * DH; t += TOT) {
        int p = t >> 7;
        g_agg[t] = hin[t] / (g_degc[p] + 1.0f);
    }
    grid_barrier();
    for (int t = tid; t < nce * DH; t += TOT) {
        int e = t >> 7, j = t & 127;
        int cs = g_esrc[e], cd = g_edst[e];
        float w = rsqrtf(g_degc[cs] + 1.0f) * rsqrtf(g_degc[cd] + 1.0f);
        atomicAdd(&g_agg[cd * DH + j], w * hin[cs * DH + j]);
    }
    grid_barrier();
    for (int o = tid; o < nk * DH; o += TOT) {
        int p = o >> 7, j = o & 127;
        const float* arow = &g_agg[p * DH];
        float v = b[j];
        #pragma unroll 16
        for (int k = 0; k < DH; k++) v = fmaf(arow[k], W[k * DH + j], v);
        v = fmaxf(v, 0.0f);
        v = (v - rm[j]) * rsqrtf(rv[j] + BN_EPSV) * g[j] + be[j];
        if (do_pool) atomicMaxF(&g_pool[g_kgraph[p] * DH + j], v);
        else hout[o] = v;
    }
    grid_barrier();
}

__global__ void __launch_bounds__(NT, 1) mega_kernel(
    const float* __restrict__ x, const int* __restrict__ ei,
    const int* __restrict__ batch, const float* __restrict__ tw,
    const float* __restrict__ W1, const float* __restrict__ b1,
    const float* __restrict__ g1, const float* __restrict__ be1,
    const float* __restrict__ rm1, const float* __restrict__ rv1,
    const float* __restrict__ W2, const float* __restrict__ b2,
    const float* __restrict__ g2, const float* __restrict__ be2,
    const float* __restrict__ rm2, const float* __restrict__ rv2,
    const float* __restrict__ W3, const float* __restrict__ b3,
    const float* __restrict__ g3, const float* __restrict__ be3,
    const float* __restrict__ rm3, const float* __restrict__ rv3,
    const float* __restrict__ linW, const float* __restrict__ linb,
    float* __restrict__ out) {

    __shared__ int4  s_e4[EPB];       // 43.3 KB edge-src slice (overlaid by s_h later)
    __shared__ float s_red[32];
    __shared__ int   s_lo, s_hi;
    float (*s_h)[DH] = (float(*)[DH])s_e4;   // overlay for fused MLP

    const int tid = blockIdx.x * NT + threadIdx.x;

    // ---- phase A: issue edge-src prefetch into SMEM (non-blocking) ----
    {
        const int4* s4 = (const int4*)ei;
        const int base4 = blockIdx.x * EPB;
        for (int k = threadIdx.x; k < EPB; k += NT) {
            int q = base4 + k;
            if (q < E4TOT) cp_async16(&s_e4[k], &s4[q]);
        }
        asm volatile("cp.async.commit_group;" ::: "memory");
    }

    // ---- phase B: softmax+keep (blocks < BB) | pool-init + L2 warm (others) ----
    if (blockIdx.x < BB) {
        const int b = blockIdx.x;
        if (threadIdx.x == 0)       s_lo = lbound(batch, b);
        else if (threadIdx.x == 32) s_hi = lbound(batch, b + 1);
        __syncthreads();
        const int lo = s_lo, hi = s_hi;
        const float tw0 = tw[0], tw1 = tw[1];

        float m = -FLT_MAX;
        for (int i = lo + threadIdx.x; i < hi; i += NT) {
            float2 xv = ((const float2*)x)[i];
            float l = xv.x * tw0 + xv.y * tw1;
            g_logit[i] = l;
            m = fmaxf(m, l);
        }
        m = blk_max(m, s_red);
        float sum = 0.0f;
        for (int i = lo + threadIdx.x; i < hi; i += NT) {
            float e = expf(g_logit[i] - m);
            g_logit[i] = e;
            sum += e;
        }
        sum = blk_sum(sum, s_red);
        const float thr = fminf(1.0f / sum - TOLV, MIN_SCORE);
        for (int i = lo + threadIdx.x; i < hi; i += NT) {
            float s = g_logit[i] / sum;
            if (s > thr) {
                int pos = atomicAdd(&g_nk, 1);
                g_kidx[pos] = i;
                g_kgraph[pos] = b;
                g_cidx[i] = pos;
                atomicOr(&g_kbits[i >> 5], 1u << (i & 31));
                float2 xv = ((const float2*)x)[i];
                g_h0[2 * pos + 0] = xv.x * s;
                g_h0[2 * pos + 1] = xv.y * s;
                g_degc[pos] = 0.0f;
            }
        }
    } else {
        // pool init (blocks 64..71 cover exactly BB*DH = 8192 slots)
        if (blockIdx.x < BB + 8)
            g_pool[(blockIdx.x - BB) * NT + threadIdx.x] = -FLT_MAX;
        // warm W2/W3/linW into L2 for the MLP phase
        int t = (blockIdx.x - BB) * NT + threadIdx.x;
        float acc = 0.0f;
        if (t < DH * DH)              acc = __ldg(&W2[t]);
        else if (t < 2 * DH * DH)     acc = __ldg(&W3[t - DH * DH]);
        else if (t < 2 * DH * DH + DH * NCLS) acc = __ldg(&linW[t - 2 * DH * DH]);
        if (acc == 1.2345678e33f) g_sink = acc;   // never true; keeps loads live
    }
    grid_barrier();   // B1: keep-bits final
    const int nk = *(volatile int*)&g_nk;

    // ---- phase C: edge scan from SMEM (lazy dst) ----
    {
        asm volatile("cp.async.wait_group 0;" ::: "memory");
        __syncthreads();
        const int* dArr = ei + EE;
        const int base4 = blockIdx.x * EPB;
        for (int k = threadIdx.x; k < EPB; k += NT) {
            int q = base4 + k;
            if (q >= E4TOT) break;
            int4 ss = s_e4[k];
            #pragma unroll
            for (int u = 0; u < 4; u++) {
                int s = (u == 0) ? ss.x : (u == 1) ? ss.y : (u == 2) ? ss.z : ss.w;
                if ((g_kbits[s >> 5] >> (s & 31)) & 1u) {
                    int d = __ldg(&dArr[4 * q + u]);
                    if ((g_kbits[d >> 5] >> (d & 31)) & 1u) {
                        int pos = atomicAdd(&g_nce, 1);
                        g_esrc[pos] = g_cidx[s];
                        g_edst[pos] = g_cidx[d];
                        atomicAdd(&g_degc[g_cidx[d]], 1.0f);
                    }
                }
            }
        }
    }
    grid_barrier();   // B2: edges + degrees final
    const int nce = *(volatile int*)&g_nce;

    if (nce == 0) {
        // ---- fused 3-layer per-node MLP + pool (deg == 1 -> all norms == 1) ----
        const int sub = threadIdx.x >> 7;
        const int j = threadIdx.x & 127;
        for (int base = blockIdx.x * SUB; base < nk; base += GRID * SUB) {
            const int p = base + sub;
            const bool act = (p < nk);
            if (act) {
                float v = g_h0[2 * p] * W1[j] + g_h0[2 * p + 1] * W1[DH + j] + b1[j];
                v = fmaxf(v, 0.0f);
                v = (v - rm1[j]) * rsqrtf(rv1[j] + BN_EPSV) * g1[j] + be1[j];
                s_h[sub][j] = v;
            }
            __syncthreads();
            float v2 = b2[j];
            if (act) {
                #pragma unroll 16
                for (int k = 0; k < DH; k++) v2 = fmaf(s_h[sub][k], W2[k * DH + j], v2);
                v2 = fmaxf(v2, 0.0f);
                v2 = (v2 - rm2[j]) * rsqrtf(rv2[j] + BN_EPSV) * g2[j] + be2[j];
            }
            __syncthreads();
            if (act) s_h[sub][j] = v2;
            __syncthreads();
            if (act) {
                float v3 = b3[j];
                #pragma unroll 16
                for (int k = 0; k < DH; k++) v3 = fmaf(s_h[sub][k], W3[k * DH + j], v3);
                v3 = fmaxf(v3, 0.0f);
                v3 = (v3 - rm3[j]) * rsqrtf(rv3[j] + BN_EPSV) * g3[j] + be3[j];
                atomicMaxF(&g_pool[g_kgraph[p] * DH + j], v3);
            }
            __syncthreads();
        }
        grid_barrier();   // B3: pool final
    } else {
        // ---- general path with edge aggregation ----
        for (int t = tid; t < nk * 2; t += TOT) {
            int p = t >> 1;
            g_agg[t] = g_h0[t] / (g_degc[p] + 1.0f);
        }
        grid_barrier();
        for (int t = tid; t < nce * 2; t += TOT) {
            int e = t >> 1, j = t & 1;
            int cs = g_esrc[e], cd = g_edst[e];
            float w = rsqrtf(g_degc[cs] + 1.0f) * rsqrtf(g_degc[cd] + 1.0f);
            atomicAdd(&g_agg[cd * 2 + j], w * g_h0[cs * 2 + j]);
        }
        grid_barrier();
        for (int o = tid; o < nk * DH; o += TOT) {
            int p = o >> 7, j = o & 127;
            float v = g_agg[2 * p] * W1[j] + g_agg[2 * p + 1] * W1[DH + j] + b1[j];
            v = fmaxf(v, 0.0f);
            v = (v - rm1[j]) * rsqrtf(rv1[j] + BN_EPSV) * g1[j] + be1[j];
            g_hA[o] = v;
        }
        grid_barrier();
        gcn_layer128(tid, nk, nce, g_hA, g_hB, W2, b2, g2, be2, rm2, rv2, false);
        gcn_layer128(tid, nk, nce, g_hB, g_hA, W3, b3, g3, be3, rm3, rv3, true);
    }

    // ---- final linear + log_softmax (block 0) + state cleanup (block 1) ----
    if (blockIdx.x == 0 && threadIdx.x < BB) {
        int b = threadIdx.x;
        float z[NCLS];
        #pragma unroll
        for (int c = 0; c < NCLS; c++) z[c] = linb[c];
        for (int j = 0; j < DH; j++) {
            float pv = g_pool[b * DH + j];
            #pragma unroll
            for (int c = 0; c < NCLS; c++) z[c] = fmaf(pv, linW[j * NCLS + c], z[c]);
        }
        float mm = fmaxf(z[0], fmaxf(z[1], z[2]));
        float s = expf(z[0] - mm) + expf(z[1] - mm) + expf(z[2] - mm);
        float lse = mm + logf(s);
        #pragma unroll
        for (int c = 0; c < NCLS; c++) out[b * NCLS + c] = z[c] - lse;
    }
    if (blockIdx.x == 1) {
        // restore zero-state for the next run (nk/kbits read only pre-B2)
        for (int i = threadIdx.x; i < nk; i += NT)
            g_kbits[g_kidx[i] >> 5] = 0u;
        if (threadIdx.x == 0) { g_nk = 0; g_nce = 0; }
    }
}

// ---------------- launcher ----------------
extern "C" void kernel_launch(void* const* d_in, const int* in_sizes, int n_in,
                              void* d_out, int out_size) {
    const float* x      = (const float*)d_in[0];
    const int*   ei     = (const int*)  d_in[1];
    const int*   batch  = (const int*)  d_in[2];
    const float* topk_w = (const float*)d_in[3];
    const float* W1 = (const float*)d_in[4],  *b1 = (const float*)d_in[5];
    const float* g1 = (const float*)d_in[6],  *be1= (const float*)d_in[7];
    const float* rm1= (const float*)d_in[8],  *rv1= (const float*)d_in[9];
    const float* W2 = (const float*)d_in[10], *b2 = (const float*)d_in[11];
    const float* g2 = (const float*)d_in[12], *be2= (const float*)d_in[13];
    const float* rm2= (const float*)d_in[14], *rv2= (const float*)d_in[15];
    const float* W3 = (const float*)d_in[16], *b3 = (const float*)d_in[17];
    const float* g3 = (const float*)d_in[18], *be3= (const float*)d_in[19];
    const float* rm3= (const float*)d_in[20], *rv3= (const float*)d_in[21];
    const float* linW = (const float*)d_in[22];
    const float* linb = (const float*)d_in[23];
    float* out = (float*)d_out;

    mega_kernel<<<GRID, NT>>>(x, ei, batch, topk_w,
                              W1, b1, g1, be1, rm1, rv1,
                              W2, b2, g2, be2, rm2, rv2,
                              W3, b3, g3, be3, rm3, rv3,
                              linW, linb, out);
}